// round 14
// baseline (speedup 1.0000x reference)
#include <cuda_runtime.h>
#include <cuda_fp16.h>
#include <cstdint>

#define N_MAX   50000
#define E_MAX   1700000
#define WMAX    512
#define N_GRAPHS 64

// ---------------- scratch (device globals) ----------------------------------
__device__ float    g_F[(size_t)N_MAX * 32];
__device__ uint4    g_H0[(size_t)N_MAX * WMAX / 8];
__device__ uint4    g_H1[(size_t)N_MAX * WMAX / 8];
__device__ uint4    g_Ht[(size_t)N_MAX * WMAX / 8];
__device__ uint4    g_Ht2[(size_t)N_MAX * WMAX / 8];
__device__ uint4    g_whh[(size_t)9 * WMAX * WMAX / 8];
__device__ float    g_dinv[N_MAX];
__device__ int      g_cnt[N_MAX];
__device__ int      g_rowptr[N_MAX + 1];
__device__ int      g_cur[N_MAX];
__device__ int      g_col[E_MAX];
__device__ float    g_wgt[E_MAX];
__device__ float    g_pool[N_GRAPHS * 32];
__device__ int      g_pcnt[N_GRAPHS];
__device__ int      g_is64;

__device__ const int d_widths[10] = {128, 128, 256, 384, 512, 512, 384, 256, 128, 32};

// ---------------- helpers -----------------------------------------------------
__device__ __forceinline__ uint32_t smem_u32(const void* p) {
    uint32_t a;
    asm("{ .reg .u64 t; cvta.to.shared.u64 t, %1; cvt.u32.u64 %0, t; }" : "=r"(a) : "l"(p));
    return a;
}
__device__ __forceinline__ int ld_idx(const void* p, long i) {
    if (g_is64) return (int)((const long long*)p)[i];
    return ((const int*)p)[i];
}

// ---------------- setup: cnt=1, pool=0, dtype detect, pcnt ---------------------
__global__ void setup_kernel(const void* edge, const void* batch, int n) {
    int i = blockIdx.x * blockDim.x + threadIdx.x;
    if (i == 0) {
        const int* p = (const int*)edge;
        bool is64 = true;
        for (int k = 0; k < 8; k++)
            if (p[2 * k + 1] != 0) is64 = false;
        g_is64 = is64 ? 1 : 0;
    }
    if (blockIdx.x == 0 && threadIdx.x >= 64 && threadIdx.x < 128) {
        // per-graph counts: batch is sorted -> binary searches (needs g_is64;
        // recompute locally to avoid dependence on thread 0's store)
        const int* p = (const int*)edge;
        bool is64 = true;
        for (int k = 0; k < 8; k++)
            if (p[2 * k + 1] != 0) is64 = false;
        int b = threadIdx.x - 64;
        auto bld = [&](long j) -> int {
            if (is64) return (int)((const long long*)batch)[j];
            return ((const int*)batch)[j];
        };
        int lo = 0, hi = n;
        while (lo < hi) { int m = (lo + hi) >> 1; if (bld(m) < b) lo = m + 1; else hi = m; }
        int start = lo;
        lo = 0; hi = n;
        while (lo < hi) { int m = (lo + hi) >> 1; if (bld(m) < b + 1) lo = m + 1; else hi = m; }
        g_pcnt[b] = lo - start;
    }
    if (i < n) g_cnt[i] = 1;
    if (i < N_GRAPHS * 32) g_pool[i] = 0.f;
}
__global__ void count_kernel(const void* edge, int E) {
    int i = blockIdx.x * blockDim.x + threadIdx.x;
    if (i < E) atomicAdd(&g_cnt[ld_idx(edge, (long)E + i)], 1);
}
__global__ void scan_kernel(int n) {
    __shared__ int warp_sums[32];
    int tid = threadIdx.x;
    int chunk = (n + 1023) / 1024;
    int s = tid * chunk;
    int e = s + chunk; if (e > n) e = n; if (s > n) s = n;
    int sum = 0;
    for (int i = s; i < e; i++) sum += g_cnt[i];
    int lane = tid & 31, w = tid >> 5;
    int v = sum;
#pragma unroll
    for (int o = 1; o < 32; o <<= 1) {
        int t = __shfl_up_sync(0xFFFFFFFFu, v, o);
        if (lane >= o) v += t;
    }
    if (lane == 31) warp_sums[w] = v;
    __syncthreads();
    if (w == 0) {
        int x = warp_sums[lane];
#pragma unroll
        for (int o = 1; o < 32; o <<= 1) {
            int t = __shfl_up_sync(0xFFFFFFFFu, x, o);
            if (lane >= o) x += t;
        }
        warp_sums[lane] = x;
    }
    __syncthreads();
    int excl = v - sum + (w > 0 ? warp_sums[w - 1] : 0);
    int run = excl;
    for (int i = s; i < e; i++) {
        int c = g_cnt[i];
        g_rowptr[i] = run;
        g_cur[i] = run;
        g_dinv[i] = rsqrtf((float)c);
        run += c;
    }
    if (tid == 1023) g_rowptr[n] = run;
}
__global__ void fill_kernel(const void* edge, int E, int n) {
    int i = blockIdx.x * blockDim.x + threadIdx.x;
    if (i < E) {
        int src = ld_idx(edge, i);
        int dst = ld_idx(edge, (long)E + i);
        int pos = atomicAdd(&g_cur[dst], 1);
        g_col[pos] = src;
        g_wgt[pos] = g_dinv[src] * g_dinv[dst];
    } else if (i < E + n) {
        int node = i - E;
        int pos = atomicAdd(&g_cur[node], 1);
        g_col[pos] = node;
        g_wgt[pos] = g_dinv[node] * g_dinv[node];
    }
}

// ---------------- SpMM body (fp16 gather, fp32 acc, fp16 out) -----------------
__device__ __forceinline__ void acc8(float* acc, const uint4& v, float w) {
    float2 f0 = __half22float2(*(const half2*)&v.x);
    float2 f1 = __half22float2(*(const half2*)&v.y);
    float2 f2 = __half22float2(*(const half2*)&v.z);
    float2 f3 = __half22float2(*(const half2*)&v.w);
    acc[0] += w * f0.x; acc[1] += w * f0.y;
    acc[2] += w * f1.x; acc[3] += w * f1.y;
    acc[4] += w * f2.x; acc[5] += w * f2.y;
    acc[6] += w * f3.x; acc[7] += w * f3.y;
}

__device__ __forceinline__ void spmm_body(
    const uint4* __restrict__ in, uint4* __restrict__ out,
    const float* __restrict__ bias, int act, int W8,
    int nodeBase, int nodeLim, int sb, int nthreads)
{
    int ypb = nthreads / W8;
    int yi = threadIdx.x / W8;
    int t  = threadIdx.x % W8;
    if (yi >= ypb) return;
    int node = nodeBase + sb * ypb + yi;
    if (node >= nodeLim) return;
    int s = g_rowptr[node], e = g_rowptr[node + 1];
    float acc[8];
#pragma unroll
    for (int j = 0; j < 8; j++) acc[j] = 0.f;
    int p = s;
    for (; p + 3 < e; p += 4) {
        int c0 = g_col[p], c1 = g_col[p + 1], c2 = g_col[p + 2], c3 = g_col[p + 3];
        float w0 = g_wgt[p], w1 = g_wgt[p + 1], w2 = g_wgt[p + 2], w3 = g_wgt[p + 3];
        uint4 v0 = in[(size_t)c0 * W8 + t];
        uint4 v1 = in[(size_t)c1 * W8 + t];
        uint4 v2 = in[(size_t)c2 * W8 + t];
        uint4 v3 = in[(size_t)c3 * W8 + t];
        acc8(acc, v0, w0); acc8(acc, v1, w1);
        acc8(acc, v2, w2); acc8(acc, v3, w3);
    }
    for (; p < e; p++) {
        uint4 v0 = in[(size_t)g_col[p] * W8 + t];
        acc8(acc, v0, g_wgt[p]);
    }
    if (bias) {
#pragma unroll
        for (int j = 0; j < 8; j++) acc[j] += bias[8 * t + j];
    }
    if (act == 1) {
#pragma unroll
        for (int j = 0; j < 8; j++) acc[j] = fmaxf(acc[j], 0.f);
    } else if (act == 2) {
#pragma unroll
        for (int j = 0; j < 8; j++) acc[j] = acc[j] > 0.f ? acc[j] : 0.01f * acc[j];
    }
    uint4 ov;
    half2 h0 = __float22half2_rn(make_float2(acc[0], acc[1]));
    half2 h1 = __float22half2_rn(make_float2(acc[2], acc[3]));
    half2 h2 = __float22half2_rn(make_float2(acc[4], acc[5]));
    half2 h3 = __float22half2_rn(make_float2(acc[6], acc[7]));
    ov.x = *(uint32_t*)&h0; ov.y = *(uint32_t*)&h1;
    ov.z = *(uint32_t*)&h2; ov.w = *(uint32_t*)&h3;
    out[(size_t)node * W8 + t] = ov;
}

__global__ __launch_bounds__(128) void spmm_h_kernel(
    const uint4* __restrict__ in, uint4* __restrict__ out,
    const float* __restrict__ bias, int act, int W8, int nodeBase, int nodeLim)
{
    spmm_body(in, out, bias, act, W8, nodeBase, nodeLim, blockIdx.x, 128);
}

// final layer: SpMM at W=32 fused with pooling atomics
__global__ void spmm_pool_kernel(const float* __restrict__ in, const void* batch,
                                 const float* __restrict__ bias, int n) {
    int node = blockIdx.x * blockDim.y + threadIdx.y;
    if (node >= n) return;
    int tid = threadIdx.x;
    int s = g_rowptr[node], e = g_rowptr[node + 1];
    float acc = 0.f;
    int p = s;
    for (; p + 1 < e; p += 2) {
        int c0 = g_col[p], c1 = g_col[p + 1];
        float w0 = g_wgt[p], w1 = g_wgt[p + 1];
        acc += w0 * in[(size_t)c0 * 32 + tid] + w1 * in[(size_t)c1 * 32 + tid];
    }
    if (p < e) acc += g_wgt[p] * in[(size_t)g_col[p] * 32 + tid];
    float v = acc + bias[tid];
    int b = ld_idx(batch, node);
    atomicAdd(&g_pool[b * 32 + tid], v);
}

// ---------------- x -> fp16 convert -------------------------------------------
__global__ void f2h_kernel(const float2* __restrict__ in, uint32_t* __restrict__ out,
                           long total2) {
    long i = (long)blockIdx.x * blockDim.x + threadIdx.x;
    if (i < total2) {
        float2 v = in[i];
        half2 h = __float22half2_rn(v);
        out[i] = *(uint32_t*)&h;
    }
}

// ---------------- fused weight transpose -> fp16 ------------------------------
struct TParams { const float* W[9]; };
__global__ void transpose_all_kernel(TParams tp, __half* whh) {
    int l = blockIdx.z;
    int K = d_widths[l], N = d_widths[l + 1];
    int k0 = blockIdx.x * 32, n0 = blockIdx.y * 32;
    if (k0 >= K || n0 >= N) return;
    const float* W = tp.W[l];
    __half* Wt = whh + (size_t)l * WMAX * WMAX;
    __shared__ float t[32][33];
    int x = threadIdx.x, y = threadIdx.y;
    for (int i = y; i < 32; i += 8) {
        int k = k0 + i, nn = n0 + x;
        t[i][x] = (k < K && nn < N) ? W[(size_t)k * N + nn] : 0.f;
    }
    __syncthreads();
    for (int i = y; i < 32; i += 8) {
        int nn = n0 + i, k = k0 + x;
        if (nn < N && k < K) Wt[(size_t)nn * K + k] = __float2half_rn(t[x][i]);
    }
}

// ---------------- FP16 mma.sync GEMM body (m16n8k16, cp.async) ----------------
#define S4 20
#define PLANE_WORDS (128 * S4)
#define STAGE_WORDS (2 * PLANE_WORDS)
#define GEMM_SMEM_BYTES (2 * STAGE_WORDS * 4)   // 40960 B

__device__ __forceinline__ void mma16h(float* d, const uint32_t* a, const uint32_t* b) {
    asm volatile(
        "mma.sync.aligned.m16n8k16.row.col.f32.f16.f16.f32 "
        "{%0,%1,%2,%3}, {%4,%5,%6,%7}, {%8,%9}, {%0,%1,%2,%3};"
        : "+f"(d[0]), "+f"(d[1]), "+f"(d[2]), "+f"(d[3])
        : "r"(a[0]), "r"(a[1]), "r"(a[2]), "r"(a[3]), "r"(b[0]), "r"(b[1]));
}
__device__ __forceinline__ void cp_async16(uint32_t dst, const void* src, int sz) {
    asm volatile("cp.async.ca.shared.global [%0], [%1], 16, %2;"
                 :: "r"(dst), "l"(src), "r"(sz) : "memory");
}

// mode: 0 = fp32 out (C), 2 = fp16 out (Oh)
__device__ __forceinline__ void gemm_body(
    const uint32_t* __restrict__ Ah, const uint32_t* __restrict__ Bh,
    const float* __restrict__ bias, float* __restrict__ C,
    uint32_t* __restrict__ Oh,
    int Mbase, int Mlim, int K, int Nfull, int act, int mode,
    int bx, int by, uint32_t* smw)
{
    uint32_t sb = smem_u32(smw);
    int tid = threadIdx.x;
    int wid = tid >> 5, lid = tid & 31;
    int wm = wid >> 2;
    int wn = wid & 3;
    int g  = lid >> 2;
    int tg = lid & 3;
    int m0 = Mbase + by * 128;
    int n0 = bx * 128;
    int Kw = K >> 1;

    float acc[4][4][4];
#pragma unroll
    for (int mi = 0; mi < 4; mi++)
#pragma unroll
        for (int ni = 0; ni < 4; ni++)
#pragma unroll
            for (int q = 0; q < 4; q++) acc[mi][ni][q] = 0.f;

    int KT = K >> 5;

    auto load_tile = [&](int kt, int b) {
        int kw = kt << 4;
        uint32_t base = sb + (uint32_t)(b * STAGE_WORDS) * 4u;
#pragma unroll
        for (int q = 0; q < 2; q++) {
            int i = tid + q * 256;
            int r = i >> 2, c = i & 3;
            uint32_t doff = (uint32_t)(r * S4 + c * 4) * 4u;
            bool okA = (m0 + r) < Mlim;
            cp_async16(base + doff, Ah + (size_t)(m0 + r) * Kw + kw + c * 4, okA ? 16 : 0);
            bool okB = (n0 + r) < Nfull;
            cp_async16(base + PLANE_WORDS * 4u + doff,
                       Bh + (size_t)(n0 + r) * Kw + kw + c * 4, okB ? 16 : 0);
        }
    };

    load_tile(0, 0);
    asm volatile("cp.async.commit_group;" ::: "memory");
    if (KT > 1) load_tile(1, 1);
    asm volatile("cp.async.commit_group;" ::: "memory");

    for (int kt = 0; kt < KT; kt++) {
        asm volatile("cp.async.wait_group 1;" ::: "memory");
        __syncthreads();
        const uint32_t* AH = smw + (kt & 1) * STAGE_WORDS;
        const uint32_t* BH = AH + PLANE_WORDS;

#pragma unroll
        for (int kk = 0; kk < 2; kk++) {
            int kb = kk * 8;
            uint32_t ah[4][4], bh[4][2];
#pragma unroll
            for (int mi = 0; mi < 4; mi++) {
                int rb = wm * 64 + mi * 16;
                int o0 = (rb + g) * S4 + kb + tg;
                int o1 = (rb + g + 8) * S4 + kb + tg;
                ah[mi][0] = AH[o0]; ah[mi][1] = AH[o1];
                ah[mi][2] = AH[o0 + 4]; ah[mi][3] = AH[o1 + 4];
            }
#pragma unroll
            for (int ni = 0; ni < 4; ni++) {
                int nb = wn * 32 + ni * 8;
                int o = (nb + g) * S4 + kb + tg;
                bh[ni][0] = BH[o]; bh[ni][1] = BH[o + 4];
            }
#pragma unroll
            for (int mi = 0; mi < 4; mi++)
#pragma unroll
                for (int ni = 0; ni < 4; ni++)
                    mma16h(acc[mi][ni], ah[mi], bh[ni]);
        }
        __syncthreads();
        if (kt + 2 < KT) load_tile(kt + 2, kt & 1);
        asm volatile("cp.async.commit_group;" ::: "memory");
    }

#pragma unroll
    for (int mi = 0; mi < 4; mi++) {
        int row0 = m0 + wm * 64 + mi * 16 + g;
        int row1 = row0 + 8;
#pragma unroll
        for (int ni = 0; ni < 4; ni++) {
            int col = n0 + wn * 32 + ni * 8 + 2 * tg;
            if (col >= Nfull) continue;
            float bx2 = 0.f, by2 = 0.f;
            if (bias) { bx2 = bias[col]; by2 = bias[col + 1]; }
#pragma unroll
            for (int h = 0; h < 2; h++) {
                int row = h ? row1 : row0;
                if (row >= Mlim) continue;
                float vx = acc[mi][ni][h * 2 + 0] + bx2;
                float vy = acc[mi][ni][h * 2 + 1] + by2;
                if (act == 1) { vx = fmaxf(vx, 0.f); vy = fmaxf(vy, 0.f); }
                else if (act == 2) {
                    vx = vx > 0.f ? vx : 0.01f * vx;
                    vy = vy > 0.f ? vy : 0.01f * vy;
                }
                if (mode == 2) {
                    half2 hv = __float22half2_rn(make_float2(vx, vy));
                    Oh[(size_t)row * (Nfull >> 1) + (col >> 1)] = *(uint32_t*)&hv;
                } else {
                    *(float2*)(C + (size_t)row * Nfull + col) = make_float2(vx, vy);
                }
            }
        }
    }
}

__global__ __launch_bounds__(256, 2) void gemm_h1_kernel(
    const uint32_t* __restrict__ Ah, const uint32_t* __restrict__ Bh,
    const float* __restrict__ bias, float* __restrict__ C,
    uint32_t* __restrict__ Oh, int Mbase, int Mlim, int K, int Nfull, int act, int mode)
{
    extern __shared__ uint32_t smw[];
    gemm_body(Ah, Bh, bias, C, Oh, Mbase, Mlim, K, Nfull, act, mode,
              blockIdx.x, blockIdx.y, smw);
}

// fused: gemm(chunk0 rows) + spmm(chunk1 nodes), Bresenham-interleaved in bid space
__global__ __launch_bounds__(256, 2) void fused_gs_kernel(
    const uint32_t* __restrict__ Ah, const uint32_t* __restrict__ Bh,
    const float* __restrict__ gbias, float* __restrict__ C,
    uint32_t* __restrict__ Oh, int Mbase, int Mlim, int K, int Nfull, int gact, int gmode,
    int gGX, int gTiles, int Total,
    const uint4* __restrict__ sin, uint4* __restrict__ sout,
    const float* __restrict__ sbias, int sact, int W8, int sBase, int sLim)
{
    extern __shared__ uint32_t smw[];
    int bid = blockIdx.x;
    long fb  = ((long)bid * gTiles) / Total;
    long fb1 = ((long)(bid + 1) * gTiles) / Total;
    if (fb1 > fb) {
        int gi = (int)fb;
        gemm_body(Ah, Bh, gbias, C, Oh, Mbase, Mlim, K, Nfull, gact, gmode,
                  gi % gGX, gi / gGX, smw);
    } else {
        int si = bid - (int)fb;
        spmm_body(sin, sout, sbias, sact, W8, sBase, sLim, si, 256);
    }
}

// ---------------- pool tail ----------------------------------------------------
__global__ void pool_fin_kernel(float* out) {
    int i = blockIdx.x * blockDim.x + threadIdx.x;
    if (i < N_GRAPHS * 32) {
        int b = i >> 5;
        out[i] = g_pool[i] / fmaxf((float)g_pcnt[b], 1.0f);
    }
}

// ---------------- host driver --------------------------------------------------
static inline int cdiv(int a, int b) { return (a + b - 1) / b; }

static void launch_S(const uint4* in, uint4* out, const float* bias, int act,
                     int W, int n0b, int n1b) {
    int W8 = W / 8;
    int ypb = 128 / W8; if (ypb < 1) ypb = 1;
    spmm_h_kernel<<<cdiv(n1b - n0b, ypb), 128>>>(in, out, bias, act, W8, n0b, n1b);
}

static void launch_G(const uint32_t* A, const uint32_t* w, const float* bias,
                     float* C, uint32_t* Oh, int Mbase, int Mlim,
                     int K, int N, int act, int mode) {
    dim3 grid(cdiv(N, 128), cdiv(Mlim - Mbase, 128));
    gemm_h1_kernel<<<grid, 256, GEMM_SMEM_BYTES>>>(A, w, bias, C, Oh,
                                                   Mbase, Mlim, K, N, act, mode);
}

// pipelined S->G pair: S(c0); fused-interleaved[G(c0) || S(c1)]; G(c1)
static void pipe_pair(const uint4* Sin, uint4* Sout, const float* Sbias, int Sact, int SW,
                      const uint32_t* Gw, const float* Gbias, float* GC, uint32_t* GOh,
                      int GN, int Gact, int Gmode, int n, int nh) {
    int K = SW;
    launch_S(Sin, Sout, Sbias, Sact, SW, 0, nh);
    int gGX = cdiv(GN, 128), gGY = cdiv(nh, 128);
    int gTiles = gGX * gGY;
    int W8 = SW / 8;
    int ypb = 256 / W8;
    int sBlocks = cdiv(n - nh, ypb);
    int Total = gTiles + sBlocks;
    fused_gs_kernel<<<Total, 256, GEMM_SMEM_BYTES>>>(
        (const uint32_t*)Sout, Gw, Gbias, GC, GOh, 0, nh, K, GN, Gact, Gmode,
        gGX, gTiles, Total,
        Sin, Sout, Sbias, Sact, W8, nh, n);
    launch_G((const uint32_t*)Sout, Gw, Gbias, GC, GOh, nh, n, K, GN, Gact, Gmode);
}

extern "C" void kernel_launch(void* const* d_in, const int* in_sizes, int n_in,
                              void* d_out, int out_size) {
    const float* x     = (const float*)d_in[0];
    const void*  edge  = d_in[1];
    const void*  batch = d_in[2];
    TParams tp;
    const float* bl[9];
    for (int i = 0; i < 9; i++) {
        tp.W[i] = (const float*)d_in[3 + 2 * i];
        bl[i]   = (const float*)d_in[4 + 2 * i];
    }
    int n = in_sizes[2];
    int E = in_sizes[1] / 2;
    int nh = ((n / 2) + 127) & ~127;
    if (nh >= n) nh = (n > 256) ? n - 128 : n / 2;

    float *F;
    uint4 *H0, *H1, *Ht, *Ht2, *whh;
    cudaGetSymbolAddress((void**)&F,   g_F);
    cudaGetSymbolAddress((void**)&H0,  g_H0);
    cudaGetSymbolAddress((void**)&H1,  g_H1);
    cudaGetSymbolAddress((void**)&Ht,  g_Ht);
    cudaGetSymbolAddress((void**)&Ht2, g_Ht2);
    cudaGetSymbolAddress((void**)&whh, g_whh);

    cudaFuncSetAttribute(gemm_h1_kernel, cudaFuncAttributeMaxDynamicSharedMemorySize,
                         GEMM_SMEM_BYTES);
    cudaFuncSetAttribute(fused_gs_kernel, cudaFuncAttributeMaxDynamicSharedMemorySize,
                         GEMM_SMEM_BYTES);

    // --- setup: CSR build + fp16 weight transpose + x->fp16 ---
    setup_kernel<<<cdiv(n, 256), 256>>>(edge, batch, n);
    transpose_all_kernel<<<dim3(16, 16, 9), dim3(32, 8)>>>(tp, (__half*)whh);
    f2h_kernel<<<cdiv(n * 64, 256), 256>>>((const float2*)x, (uint32_t*)H0, (long)n * 64);
    count_kernel<<<cdiv(E, 256), 256>>>(edge, E);
    scan_kernel<<<1, 1024>>>(n);
    fill_kernel<<<cdiv(E + n, 256), 256>>>(edge, E, n);

    static const int widths[10] = {128, 128, 256, 384, 512, 512, 384, 256, 128, 32};
    static const int acts[9]    = {1, 1, 2, 1, 2, 2, 1, 1, 0};
    const uint32_t* wptr[9];
    for (int l = 0; l < 9; l++)
        wptr[l] = (const uint32_t*)whh + (size_t)l * WMAX * WMAX / 2;

    // --- layers 0..4 (agg-first): S(Hin->Ht), G(Ht->Hout) pipelined ---
    for (int l = 0; l < 5; l++) {
        uint4* Hin  = (l & 1) ? H1 : H0;
        uint4* Hout = (l & 1) ? H0 : H1;
        pipe_pair(Hin, Ht, nullptr, 0, widths[l],
                  wptr[l], bl[l], nullptr, (uint32_t*)Hout,
                  widths[l + 1], acts[l], 2, n, nh);
    }
    // activations now in H1

    // --- layer 5: full G (H1 -> Ht) ---
    launch_G((const uint32_t*)H1, wptr[5], nullptr, nullptr, (uint32_t*)Ht,
             0, n, 512, 384, 0, 2);
    // --- pair (S5, G6): S5(Ht->H0 +bias5/act5), G6(H0->Ht2) ---
    pipe_pair(Ht, H0, bl[5], acts[5], 384,
              wptr[6], nullptr, nullptr, (uint32_t*)Ht2, 256, 0, 2, n, nh);
    // --- pair (S6, G7): S6(Ht2->H1 +bias6/act6), G7(H1->Ht) ---
    pipe_pair(Ht2, H1, bl[6], acts[6], 256,
              wptr[7], nullptr, nullptr, (uint32_t*)Ht, 128, 0, 2, n, nh);
    // --- pair (S7, G8): S7(Ht->H0 +bias7/act7), G8(H0->F fp32) ---
    pipe_pair(Ht, H0, bl[7], acts[7], 128,
              wptr[8], nullptr, F, nullptr, 32, 0, 0, n, nh);
    // --- final: fused spmm+pool over F ---
    spmm_pool_kernel<<<cdiv(n, 4), dim3(32, 4)>>>(F, batch, bl[8], n);

    // --- pool finalize ---
    pool_fin_kernel<<<cdiv(N_GRAPHS * 32, 256), 256>>>((float*)d_out);
}

// round 15
// speedup vs baseline: 1.3038x; 1.3038x over previous
#include <cuda_runtime.h>
#include <cuda_fp16.h>
#include <cstdint>

#define N_MAX   50000
#define E_MAX   1700000
#define WMAX    512
#define N_GRAPHS 64

// ---------------- scratch (device globals) ----------------------------------
__device__ float    g_F[(size_t)N_MAX * 32];                   // final gemm out fp32
__device__ uint4    g_H0[(size_t)N_MAX * WMAX / 8];            // fp16 activations (ping)
__device__ uint4    g_H1[(size_t)N_MAX * WMAX / 8];            // fp16 activations (pong)
__device__ uint4    g_Ht[(size_t)N_MAX * WMAX / 8];            // fp16 temp (agg)
__device__ uint4    g_whh[(size_t)9 * WMAX * WMAX / 8];        // fp16 weights [N][K], 9 layers
__device__ float    g_dinv[N_MAX];
__device__ int      g_cnt[N_MAX];
__device__ int      g_rowptr[N_MAX + 1];
__device__ int      g_cur[N_MAX];
__device__ int      g_col[E_MAX];
__device__ float    g_wgt[E_MAX];
__device__ float    g_pool[N_GRAPHS * 32];
__device__ int      g_pcnt[N_GRAPHS];
__device__ int      g_is64;

__device__ const int d_widths[10] = {128, 128, 256, 384, 512, 512, 384, 256, 128, 32};

// ---------------- helpers -----------------------------------------------------
__device__ __forceinline__ uint32_t smem_u32(const void* p) {
    uint32_t a;
    asm("{ .reg .u64 t; cvta.to.shared.u64 t, %1; cvt.u32.u64 %0, t; }" : "=r"(a) : "l"(p));
    return a;
}
__device__ __forceinline__ int ld_idx(const void* p, long i) {
    if (g_is64) return (int)((const long long*)p)[i];
    return ((const int*)p)[i];
}

// ---------------- setup: cnt=1, pool=0, pcnt=0, dtype detect ------------------
__global__ void setup_kernel(const void* edge, int n) {
    int i = blockIdx.x * blockDim.x + threadIdx.x;
    if (i == 0) {
        const int* p = (const int*)edge;
        bool is64 = true;
        for (int k = 0; k < 8; k++)
            if (p[2 * k + 1] != 0) is64 = false;
        g_is64 = is64 ? 1 : 0;
    }
    if (i < n) g_cnt[i] = 1;
    if (i < N_GRAPHS * 32) g_pool[i] = 0.f;
    if (i < N_GRAPHS) g_pcnt[i] = 0;
}
// merged: edge-degree count + per-graph node count
__global__ void count_pool_kernel(const void* edge, const void* batch, int E, int n) {
    int i = blockIdx.x * blockDim.x + threadIdx.x;
    if (i < E) atomicAdd(&g_cnt[ld_idx(edge, (long)E + i)], 1);
    if (i < n) atomicAdd(&g_pcnt[ld_idx(batch, i)], 1);
}
// two-pass chunked scan, single block of 1024; also computes dinv
__global__ void scan_kernel(int n) {
    __shared__ int warp_sums[32];
    int tid = threadIdx.x;
    int chunk = (n + 1023) / 1024;
    int s = tid * chunk;
    int e = s + chunk; if (e > n) e = n; if (s > n) s = n;
    int sum = 0;
    for (int i = s; i < e; i++) sum += g_cnt[i];
    int lane = tid & 31, w = tid >> 5;
    int v = sum;
#pragma unroll
    for (int o = 1; o < 32; o <<= 1) {
        int t = __shfl_up_sync(0xFFFFFFFFu, v, o);
        if (lane >= o) v += t;
    }
    if (lane == 31) warp_sums[w] = v;
    __syncthreads();
    if (w == 0) {
        int x = warp_sums[lane];
#pragma unroll
        for (int o = 1; o < 32; o <<= 1) {
            int t = __shfl_up_sync(0xFFFFFFFFu, x, o);
            if (lane >= o) x += t;
        }
        warp_sums[lane] = x;
    }
    __syncthreads();
    int excl = v - sum + (w > 0 ? warp_sums[w - 1] : 0);
    int run = excl;
    for (int i = s; i < e; i++) {
        int c = g_cnt[i];
        g_rowptr[i] = run;
        g_cur[i] = run;
        g_dinv[i] = rsqrtf((float)c);
        run += c;
    }
    if (tid == 1023) g_rowptr[n] = run;
}
// merged: fill edges + self loops
__global__ void fill_kernel(const void* edge, int E, int n) {
    int i = blockIdx.x * blockDim.x + threadIdx.x;
    if (i < E) {
        int src = ld_idx(edge, i);
        int dst = ld_idx(edge, (long)E + i);
        int pos = atomicAdd(&g_cur[dst], 1);
        g_col[pos] = src;
        g_wgt[pos] = g_dinv[src] * g_dinv[dst];
    } else if (i < E + n) {
        int node = i - E;
        int pos = atomicAdd(&g_cur[node], 1);
        g_col[pos] = node;
        g_wgt[pos] = g_dinv[node] * g_dinv[node];
    }
}

// ---------------- SpMM (fp16 gather, fp32 accumulate, fp16 out) ---------------
__device__ __forceinline__ void acc8(float* acc, const uint4& v, float w) {
    float2 f0 = __half22float2(*(const half2*)&v.x);
    float2 f1 = __half22float2(*(const half2*)&v.y);
    float2 f2 = __half22float2(*(const half2*)&v.z);
    float2 f3 = __half22float2(*(const half2*)&v.w);
    acc[0] += w * f0.x; acc[1] += w * f0.y;
    acc[2] += w * f1.x; acc[3] += w * f1.y;
    acc[4] += w * f2.x; acc[5] += w * f2.y;
    acc[6] += w * f3.x; acc[7] += w * f3.y;
}

__global__ void spmm_h_kernel(const uint4* __restrict__ in, uint4* __restrict__ out,
                              const float* __restrict__ bias, int act, int W8, int n) {
    int node = blockIdx.x * blockDim.y + threadIdx.y;
    if (node >= n) return;
    int t = threadIdx.x;
    int s = g_rowptr[node], e = g_rowptr[node + 1];
    float acc[8];
#pragma unroll
    for (int j = 0; j < 8; j++) acc[j] = 0.f;
    int p = s;
    for (; p + 3 < e; p += 4) {
        int c0 = g_col[p], c1 = g_col[p + 1], c2 = g_col[p + 2], c3 = g_col[p + 3];
        float w0 = g_wgt[p], w1 = g_wgt[p + 1], w2 = g_wgt[p + 2], w3 = g_wgt[p + 3];
        uint4 v0 = in[(size_t)c0 * W8 + t];
        uint4 v1 = in[(size_t)c1 * W8 + t];
        uint4 v2 = in[(size_t)c2 * W8 + t];
        uint4 v3 = in[(size_t)c3 * W8 + t];
        acc8(acc, v0, w0); acc8(acc, v1, w1);
        acc8(acc, v2, w2); acc8(acc, v3, w3);
    }
    for (; p < e; p++) {
        uint4 v0 = in[(size_t)g_col[p] * W8 + t];
        acc8(acc, v0, g_wgt[p]);
    }
    if (bias) {
#pragma unroll
        for (int j = 0; j < 8; j++) acc[j] += bias[8 * t + j];
    }
    if (act == 1) {
#pragma unroll
        for (int j = 0; j < 8; j++) acc[j] = fmaxf(acc[j], 0.f);
    } else if (act == 2) {
#pragma unroll
        for (int j = 0; j < 8; j++) acc[j] = acc[j] > 0.f ? acc[j] : 0.01f * acc[j];
    }
    uint4 ov;
    half2 h0 = __float22half2_rn(make_float2(acc[0], acc[1]));
    half2 h1 = __float22half2_rn(make_float2(acc[2], acc[3]));
    half2 h2 = __float22half2_rn(make_float2(acc[4], acc[5]));
    half2 h3 = __float22half2_rn(make_float2(acc[6], acc[7]));
    ov.x = *(uint32_t*)&h0; ov.y = *(uint32_t*)&h1;
    ov.z = *(uint32_t*)&h2; ov.w = *(uint32_t*)&h3;
    out[(size_t)node * W8 + t] = ov;
}

// final layer: SpMM at W=32 fused with pooling atomics
__global__ void spmm_pool_kernel(const float* __restrict__ in, const void* batch,
                                 const float* __restrict__ bias, int n) {
    int node = blockIdx.x * blockDim.y + threadIdx.y;
    if (node >= n) return;
    int tid = threadIdx.x;
    int s = g_rowptr[node], e = g_rowptr[node + 1];
    float acc = 0.f;
    int p = s;
    for (; p + 1 < e; p += 2) {
        int c0 = g_col[p], c1 = g_col[p + 1];
        float w0 = g_wgt[p], w1 = g_wgt[p + 1];
        acc += w0 * in[(size_t)c0 * 32 + tid] + w1 * in[(size_t)c1 * 32 + tid];
    }
    if (p < e) acc += g_wgt[p] * in[(size_t)g_col[p] * 32 + tid];
    float v = acc + bias[tid];
    int b = ld_idx(batch, node);
    atomicAdd(&g_pool[b * 32 + tid], v);
}

// ---------------- x -> fp16 convert -------------------------------------------
__global__ void f2h_kernel(const float2* __restrict__ in, uint32_t* __restrict__ out,
                           long total2) {
    long i = (long)blockIdx.x * blockDim.x + threadIdx.x;
    if (i < total2) {
        float2 v = in[i];
        half2 h = __float22half2_rn(v);
        out[i] = *(uint32_t*)&h;
    }
}

// ---------------- fused weight transpose -> fp16 directly ---------------------
struct TParams { const float* W[9]; };
__global__ void transpose_all_kernel(TParams tp, __half* whh) {
    int l = blockIdx.z;
    int K = d_widths[l], N = d_widths[l + 1];
    int k0 = blockIdx.x * 32, n0 = blockIdx.y * 32;
    if (k0 >= K || n0 >= N) return;
    const float* W = tp.W[l];
    __half* Wt = whh + (size_t)l * WMAX * WMAX;
    __shared__ float t[32][33];
    int x = threadIdx.x, y = threadIdx.y;
    for (int i = y; i < 32; i += 8) {
        int k = k0 + i, nn = n0 + x;
        t[i][x] = (k < K && nn < N) ? W[(size_t)k * N + nn] : 0.f;
    }
    __syncthreads();
    for (int i = y; i < 32; i += 8) {
        int nn = n0 + i, k = k0 + x;
        if (nn < N && k < K) Wt[(size_t)nn * K + k] = __float2half_rn(t[x][i]);
    }
}

// ---------------- FP16 mma.sync GEMM (m16n8k16), cp.async pipelined -----------
// C = A(fp16) * W(fp16)^T, fp32 accumulate. BM=128, BN=128, BK=32.
#define S4 20
#define PLANE_WORDS (128 * S4)
#define STAGE_WORDS (2 * PLANE_WORDS)          // A, B
#define GEMM_SMEM_BYTES (2 * STAGE_WORDS * 4)  // 40960 B double buffered

__device__ __forceinline__ void mma16h(float* d, const uint32_t* a, const uint32_t* b) {
    asm volatile(
        "mma.sync.aligned.m16n8k16.row.col.f32.f16.f16.f32 "
        "{%0,%1,%2,%3}, {%4,%5,%6,%7}, {%8,%9}, {%0,%1,%2,%3};"
        : "+f"(d[0]), "+f"(d[1]), "+f"(d[2]), "+f"(d[3])
        : "r"(a[0]), "r"(a[1]), "r"(a[2]), "r"(a[3]), "r"(b[0]), "r"(b[1]));
}
__device__ __forceinline__ void cp_async16(uint32_t dst, const void* src, int sz) {
    asm volatile("cp.async.ca.shared.global [%0], [%1], 16, %2;"
                 :: "r"(dst), "l"(src), "r"(sz) : "memory");
}

// mode: 0 = fp32 out (C), 2 = fp16 out (Oh)
__global__ __launch_bounds__(256, 2) void gemm_h1_kernel(
    const uint32_t* __restrict__ Ah, const uint32_t* __restrict__ Bh,
    const float* __restrict__ bias, float* __restrict__ C,
    uint32_t* __restrict__ Oh,
    int M, int K, int Nfull, int act, int mode)
{
    extern __shared__ uint32_t smw[];
    uint32_t sb = smem_u32(smw);
    int tid = threadIdx.x;
    int wid = tid >> 5, lid = tid & 31;
    int wm = wid >> 2;
    int wn = wid & 3;
    int g  = lid >> 2;
    int tg = lid & 3;
    int m0 = blockIdx.y * 128;
    int n0 = blockIdx.x * 128;
    int Kw = K >> 1;

    float acc[4][4][4];
#pragma unroll
    for (int mi = 0; mi < 4; mi++)
#pragma unroll
        for (int ni = 0; ni < 4; ni++)
#pragma unroll
            for (int q = 0; q < 4; q++) acc[mi][ni][q] = 0.f;

    int KT = K >> 5;

    auto load_tile = [&](int kt, int b) {
        int kw = kt << 4;
        uint32_t base = sb + (uint32_t)(b * STAGE_WORDS) * 4u;
#pragma unroll
        for (int q = 0; q < 2; q++) {
            int i = tid + q * 256;
            int r = i >> 2, c = i & 3;
            uint32_t doff = (uint32_t)(r * S4 + c * 4) * 4u;
            bool okA = (m0 + r) < M;
            cp_async16(base + doff, Ah + (size_t)(m0 + r) * Kw + kw + c * 4, okA ? 16 : 0);
            bool okB = (n0 + r) < Nfull;
            cp_async16(base + PLANE_WORDS * 4u + doff,
                       Bh + (size_t)(n0 + r) * Kw + kw + c * 4, okB ? 16 : 0);
        }
    };

    load_tile(0, 0);
    asm volatile("cp.async.commit_group;" ::: "memory");
    if (KT > 1) load_tile(1, 1);
    asm volatile("cp.async.commit_group;" ::: "memory");

    for (int kt = 0; kt < KT; kt++) {
        asm volatile("cp.async.wait_group 1;" ::: "memory");
        __syncthreads();
        const uint32_t* AH = smw + (kt & 1) * STAGE_WORDS;
        const uint32_t* BH = AH + PLANE_WORDS;

#pragma unroll
        for (int kk = 0; kk < 2; kk++) {
            int kb = kk * 8;
            uint32_t ah[4][4], bh[4][2];
#pragma unroll
            for (int mi = 0; mi < 4; mi++) {
                int rb = wm * 64 + mi * 16;
                int o0 = (rb + g) * S4 + kb + tg;
                int o1 = (rb + g + 8) * S4 + kb + tg;
                ah[mi][0] = AH[o0]; ah[mi][1] = AH[o1];
                ah[mi][2] = AH[o0 + 4]; ah[mi][3] = AH[o1 + 4];
            }
#pragma unroll
            for (int ni = 0; ni < 4; ni++) {
                int nb = wn * 32 + ni * 8;
                int o = (nb + g) * S4 + kb + tg;
                bh[ni][0] = BH[o]; bh[ni][1] = BH[o + 4];
            }
#pragma unroll
            for (int mi = 0; mi < 4; mi++)
#pragma unroll
                for (int ni = 0; ni < 4; ni++)
                    mma16h(acc[mi][ni], ah[mi], bh[ni]);
        }
        __syncthreads();
        if (kt + 2 < KT) load_tile(kt + 2, kt & 1);
        asm volatile("cp.async.commit_group;" ::: "memory");
    }

    // epilogue
#pragma unroll
    for (int mi = 0; mi < 4; mi++) {
        int row0 = m0 + wm * 64 + mi * 16 + g;
        int row1 = row0 + 8;
#pragma unroll
        for (int ni = 0; ni < 4; ni++) {
            int col = n0 + wn * 32 + ni * 8 + 2 * tg;
            if (col >= Nfull) continue;
            float bx = 0.f, by = 0.f;
            if (bias) { bx = bias[col]; by = bias[col + 1]; }
#pragma unroll
            for (int h = 0; h < 2; h++) {
                int row = h ? row1 : row0;
                if (row >= M) continue;
                float vx = acc[mi][ni][h * 2 + 0] + bx;
                float vy = acc[mi][ni][h * 2 + 1] + by;
                if (act == 1) { vx = fmaxf(vx, 0.f); vy = fmaxf(vy, 0.f); }
                else if (act == 2) {
                    vx = vx > 0.f ? vx : 0.01f * vx;
                    vy = vy > 0.f ? vy : 0.01f * vy;
                }
                if (mode == 2) {
                    half2 hv = __float22half2_rn(make_float2(vx, vy));
                    Oh[(size_t)row * (Nfull >> 1) + (col >> 1)] = *(uint32_t*)&hv;
                } else {
                    *(float2*)(C + (size_t)row * Nfull + col) = make_float2(vx, vy);
                }
            }
        }
    }
}

// ---------------- pool tail ----------------------------------------------------
__global__ void pool_fin_kernel(float* out) {
    int i = blockIdx.x * blockDim.x + threadIdx.x;
    if (i < N_GRAPHS * 32) {
        int b = i >> 5;
        out[i] = g_pool[i] / fmaxf((float)g_pcnt[b], 1.0f);
    }
}

// ---------------- host driver --------------------------------------------------
static inline int cdiv(int a, int b) { return (a + b - 1) / b; }

static void spmm_h_launch(const uint4* in, uint4* out,
                          const float* bias, int act, int W, int n) {
    int W8 = W / 8;
    int ypb = 128 / W8; if (ypb < 1) ypb = 1;
    dim3 blk(W8, ypb);
    spmm_h_kernel<<<cdiv(n, ypb), blk>>>(in, out, bias, act, W8, n);
}

extern "C" void kernel_launch(void* const* d_in, const int* in_sizes, int n_in,
                              void* d_out, int out_size) {
    const float* x     = (const float*)d_in[0];
    const void*  edge  = d_in[1];
    const void*  batch = d_in[2];
    TParams tp;
    const float* bl[9];
    for (int i = 0; i < 9; i++) {
        tp.W[i] = (const float*)d_in[3 + 2 * i];
        bl[i]   = (const float*)d_in[4 + 2 * i];
    }
    int n = in_sizes[2];
    int E = in_sizes[1] / 2;

    float *F;
    uint4 *H0, *H1, *Ht, *whh;
    cudaGetSymbolAddress((void**)&F,   g_F);
    cudaGetSymbolAddress((void**)&H0,  g_H0);
    cudaGetSymbolAddress((void**)&H1,  g_H1);
    cudaGetSymbolAddress((void**)&Ht,  g_Ht);
    cudaGetSymbolAddress((void**)&whh, g_whh);

    cudaFuncSetAttribute(gemm_h1_kernel, cudaFuncAttributeMaxDynamicSharedMemorySize,
                         GEMM_SMEM_BYTES);

    // --- setup: CSR build + fp16 weight transpose + x->fp16 (6 kernels) ---
    setup_kernel<<<cdiv(n, 256), 256>>>(edge, n);
    transpose_all_kernel<<<dim3(16, 16, 9), dim3(32, 8)>>>(tp, (__half*)whh);
    f2h_kernel<<<cdiv(n * 64, 256), 256>>>((const float2*)x, (uint32_t*)H0, (long)n * 64);
    count_pool_kernel<<<cdiv(E > n ? E : n, 256), 256>>>(edge, batch, E, n);
    scan_kernel<<<1, 1024>>>(n);
    fill_kernel<<<cdiv(E + n, 256), 256>>>(edge, E, n);

    // --- layers ---
    static const int widths[10]  = {128, 128, 256, 384, 512, 512, 384, 256, 128, 32};
    static const int acts[9]     = {1, 1, 2, 1, 2, 2, 1, 1, 0};
    static const int aggfirst[9] = {1, 1, 1, 1, 1, 0, 0, 0, 0};

    const uint4* Hin = H0;
    uint4* pong[2] = {H1, H0};
    int pp = 0;
    for (int l = 0; l < 9; l++) {
        int K = widths[l], N = widths[l + 1];
        const uint32_t* wl = (const uint32_t*)whh + (size_t)l * WMAX * WMAX / 2;
        dim3 grid(cdiv(N, 128), cdiv(n, 128));
        uint4* Hout = pong[pp];
        if (aggfirst[l]) {
            spmm_h_launch(Hin, Ht, nullptr, 0, K, n);
            gemm_h1_kernel<<<grid, 256, GEMM_SMEM_BYTES>>>(
                (const uint32_t*)Ht, wl, bl[l], nullptr, (uint32_t*)Hout,
                n, K, N, acts[l], 2);
            Hin = Hout; pp ^= 1;
        } else if (l < 8) {
            gemm_h1_kernel<<<grid, 256, GEMM_SMEM_BYTES>>>(
                (const uint32_t*)Hin, wl, nullptr, nullptr, (uint32_t*)Ht,
                n, K, N, 0, 2);
            spmm_h_launch(Ht, Hout, bl[l], acts[l], N, n);
            Hin = Hout; pp ^= 1;
        } else {
            gemm_h1_kernel<<<grid, 256, GEMM_SMEM_BYTES>>>(
                (const uint32_t*)Hin, wl, nullptr, F, nullptr,
                n, K, N, 0, 0);
            spmm_pool_kernel<<<cdiv(n, 4), dim3(32, 4)>>>(F, batch, bl[8], n);
        }
    }

    // --- pool finalize ---
    pool_fin_kernel<<<cdiv(N_GRAPHS * 32, 256), 256>>>((float*)d_out);
}

// round 16
// speedup vs baseline: 1.3215x; 1.0135x over previous
#include <cuda_runtime.h>
#include <cuda_fp16.h>
#include <cstdint>

#define N_MAX   50000
#define E_MAX   1700000
#define WMAX    512
#define N_GRAPHS 64

// ---------------- scratch (device globals) ----------------------------------
__device__ float    g_F[(size_t)N_MAX * 32];                   // final gemm out fp32
__device__ uint4    g_H0[(size_t)N_MAX * WMAX / 8];            // fp16 activations (ping)
__device__ uint4    g_H1[(size_t)N_MAX * WMAX / 8];            // fp16 activations (pong)
__device__ uint4    g_Ht[(size_t)N_MAX * WMAX / 8];            // fp16 temp (agg)
__device__ uint4    g_whh[(size_t)9 * WMAX * WMAX / 8];        // fp16 weights [N][K], 9 layers
__device__ float    g_dinv[N_MAX];
__device__ int      g_cnt[N_MAX];
__device__ int      g_rowptr[N_MAX + 1];
__device__ int      g_cur[N_MAX];
__device__ int      g_col[E_MAX];
__device__ float    g_wgt[E_MAX];
__device__ float    g_pool[N_GRAPHS * 32];
__device__ int      g_pcnt[N_GRAPHS];
__device__ int      g_is64;

__device__ const int d_widths[10] = {128, 128, 256, 384, 512, 512, 384, 256, 128, 32};

// ---------------- helpers -----------------------------------------------------
__device__ __forceinline__ uint32_t smem_u32(const void* p) {
    uint32_t a;
    asm("{ .reg .u64 t; cvta.to.shared.u64 t, %1; cvt.u32.u64 %0, t; }" : "=r"(a) : "l"(p));
    return a;
}
__device__ __forceinline__ int ld_idx(const void* p, long i) {
    if (g_is64) return (int)((const long long*)p)[i];
    return ((const int*)p)[i];
}

// ---------------- setup: cnt=1, pool=0, dtype detect, pcnt (binary search) ----
__global__ void setup_kernel(const void* edge, const void* batch, int n) {
    int i = blockIdx.x * blockDim.x + threadIdx.x;
    if (i == 0) {
        const int* p = (const int*)edge;
        bool is64 = true;
        for (int k = 0; k < 8; k++)
            if (p[2 * k + 1] != 0) is64 = false;
        g_is64 = is64 ? 1 : 0;
    }
    if (blockIdx.x == 0 && threadIdx.x >= 64 && threadIdx.x < 128) {
        // batch is sorted -> per-graph counts via binary searches (no atomics).
        // Recompute is64 locally (cannot rely on thread 0's store ordering).
        const int* p = (const int*)edge;
        bool is64 = true;
        for (int k = 0; k < 8; k++)
            if (p[2 * k + 1] != 0) is64 = false;
        int b = threadIdx.x - 64;
        auto bld = [&](long j) -> int {
            if (is64) return (int)((const long long*)batch)[j];
            return ((const int*)batch)[j];
        };
        int lo = 0, hi = n;
        while (lo < hi) { int m = (lo + hi) >> 1; if (bld(m) < b) lo = m + 1; else hi = m; }
        int start = lo;
        lo = 0; hi = n;
        while (lo < hi) { int m = (lo + hi) >> 1; if (bld(m) < b + 1) lo = m + 1; else hi = m; }
        g_pcnt[b] = lo - start;
    }
    if (i < n) g_cnt[i] = 1;
    if (i < N_GRAPHS * 32) g_pool[i] = 0.f;
}
// edge-degree count only (atomics well-spread over n counters)
__global__ void count_kernel(const void* edge, int E) {
    int i = blockIdx.x * blockDim.x + threadIdx.x;
    if (i < E) atomicAdd(&g_cnt[ld_idx(edge, (long)E + i)], 1);
}
// two-pass chunked scan, single block of 1024; also computes dinv
__global__ void scan_kernel(int n) {
    __shared__ int warp_sums[32];
    int tid = threadIdx.x;
    int chunk = (n + 1023) / 1024;
    int s = tid * chunk;
    int e = s + chunk; if (e > n) e = n; if (s > n) s = n;
    int sum = 0;
    for (int i = s; i < e; i++) sum += g_cnt[i];
    int lane = tid & 31, w = tid >> 5;
    int v = sum;
#pragma unroll
    for (int o = 1; o < 32; o <<= 1) {
        int t = __shfl_up_sync(0xFFFFFFFFu, v, o);
        if (lane >= o) v += t;
    }
    if (lane == 31) warp_sums[w] = v;
    __syncthreads();
    if (w == 0) {
        int x = warp_sums[lane];
#pragma unroll
        for (int o = 1; o < 32; o <<= 1) {
            int t = __shfl_up_sync(0xFFFFFFFFu, x, o);
            if (lane >= o) x += t;
        }
        warp_sums[lane] = x;
    }
    __syncthreads();
    int excl = v - sum + (w > 0 ? warp_sums[w - 1] : 0);
    int run = excl;
    for (int i = s; i < e; i++) {
        int c = g_cnt[i];
        g_rowptr[i] = run;
        g_cur[i] = run;
        g_dinv[i] = rsqrtf((float)c);
        run += c;
    }
    if (tid == 1023) g_rowptr[n] = run;
}
// merged: fill edges + self loops
__global__ void fill_kernel(const void* edge, int E, int n) {
    int i = blockIdx.x * blockDim.x + threadIdx.x;
    if (i < E) {
        int src = ld_idx(edge, i);
        int dst = ld_idx(edge, (long)E + i);
        int pos = atomicAdd(&g_cur[dst], 1);
        g_col[pos] = src;
        g_wgt[pos] = g_dinv[src] * g_dinv[dst];
    } else if (i < E + n) {
        int node = i - E;
        int pos = atomicAdd(&g_cur[node], 1);
        g_col[pos] = node;
        g_wgt[pos] = g_dinv[node] * g_dinv[node];
    }
}

// ---------------- SpMM (fp16 gather, fp32 accumulate, fp16 out) ---------------
__device__ __forceinline__ void acc8(float* acc, const uint4& v, float w) {
    float2 f0 = __half22float2(*(const half2*)&v.x);
    float2 f1 = __half22float2(*(const half2*)&v.y);
    float2 f2 = __half22float2(*(const half2*)&v.z);
    float2 f3 = __half22float2(*(const half2*)&v.w);
    acc[0] += w * f0.x; acc[1] += w * f0.y;
    acc[2] += w * f1.x; acc[3] += w * f1.y;
    acc[4] += w * f2.x; acc[5] += w * f2.y;
    acc[6] += w * f3.x; acc[7] += w * f3.y;
}

__global__ void spmm_h_kernel(const uint4* __restrict__ in, uint4* __restrict__ out,
                              const float* __restrict__ bias, int act, int W8, int n) {
    int node = blockIdx.x * blockDim.y + threadIdx.y;
    if (node >= n) return;
    int t = threadIdx.x;
    int s = g_rowptr[node], e = g_rowptr[node + 1];
    float acc[8];
#pragma unroll
    for (int j = 0; j < 8; j++) acc[j] = 0.f;
    int p = s;
    for (; p + 3 < e; p += 4) {
        int c0 = g_col[p], c1 = g_col[p + 1], c2 = g_col[p + 2], c3 = g_col[p + 3];
        float w0 = g_wgt[p], w1 = g_wgt[p + 1], w2 = g_wgt[p + 2], w3 = g_wgt[p + 3];
        uint4 v0 = in[(size_t)c0 * W8 + t];
        uint4 v1 = in[(size_t)c1 * W8 + t];
        uint4 v2 = in[(size_t)c2 * W8 + t];
        uint4 v3 = in[(size_t)c3 * W8 + t];
        acc8(acc, v0, w0); acc8(acc, v1, w1);
        acc8(acc, v2, w2); acc8(acc, v3, w3);
    }
    for (; p < e; p++) {
        uint4 v0 = in[(size_t)g_col[p] * W8 + t];
        acc8(acc, v0, g_wgt[p]);
    }
    if (bias) {
#pragma unroll
        for (int j = 0; j < 8; j++) acc[j] += bias[8 * t + j];
    }
    if (act == 1) {
#pragma unroll
        for (int j = 0; j < 8; j++) acc[j] = fmaxf(acc[j], 0.f);
    } else if (act == 2) {
#pragma unroll
        for (int j = 0; j < 8; j++) acc[j] = acc[j] > 0.f ? acc[j] : 0.01f * acc[j];
    }
    uint4 ov;
    half2 h0 = __float22half2_rn(make_float2(acc[0], acc[1]));
    half2 h1 = __float22half2_rn(make_float2(acc[2], acc[3]));
    half2 h2 = __float22half2_rn(make_float2(acc[4], acc[5]));
    half2 h3 = __float22half2_rn(make_float2(acc[6], acc[7]));
    ov.x = *(uint32_t*)&h0; ov.y = *(uint32_t*)&h1;
    ov.z = *(uint32_t*)&h2; ov.w = *(uint32_t*)&h3;
    out[(size_t)node * W8 + t] = ov;
}

// final layer: SpMM at W=32 fused with pooling atomics
__global__ void spmm_pool_kernel(const float* __restrict__ in, const void* batch,
                                 const float* __restrict__ bias, int n) {
    int node = blockIdx.x * blockDim.y + threadIdx.y;
    if (node >= n) return;
    int tid = threadIdx.x;
    int s = g_rowptr[node], e = g_rowptr[node + 1];
    float acc = 0.f;
    int p = s;
    for (; p + 1 < e; p += 2) {
        int c0 = g_col[p], c1 = g_col[p + 1];
        float w0 = g_wgt[p], w1 = g_wgt[p + 1];
        acc += w0 * in[(size_t)c0 * 32 + tid] + w1 * in[(size_t)c1 * 32 + tid];
    }
    if (p < e) acc += g_wgt[p] * in[(size_t)g_col[p] * 32 + tid];
    float v = acc + bias[tid];
    int b = ld_idx(batch, node);
    atomicAdd(&g_pool[b * 32 + tid], v);
}

// ---------------- x -> fp16 convert -------------------------------------------
__global__ void f2h_kernel(const float2* __restrict__ in, uint32_t* __restrict__ out,
                           long total2) {
    long i = (long)blockIdx.x * blockDim.x + threadIdx.x;
    if (i < total2) {
        float2 v = in[i];
        half2 h = __float22half2_rn(v);
        out[i] = *(uint32_t*)&h;
    }
}

// ---------------- fused weight transpose -> fp16 directly ---------------------
struct TParams { const float* W[9]; };
__global__ void transpose_all_kernel(TParams tp, __half* whh) {
    int l = blockIdx.z;
    int K = d_widths[l], N = d_widths[l + 1];
    int k0 = blockIdx.x * 32, n0 = blockIdx.y * 32;
    if (k0 >= K || n0 >= N) return;
    const float* W = tp.W[l];
    __half* Wt = whh + (size_t)l * WMAX * WMAX;
    __shared__ float t[32][33];
    int x = threadIdx.x, y = threadIdx.y;
    for (int i = y; i < 32; i += 8) {
        int k = k0 + i, nn = n0 + x;
        t[i][x] = (k < K && nn < N) ? W[(size_t)k * N + nn] : 0.f;
    }
    __syncthreads();
    for (int i = y; i < 32; i += 8) {
        int nn = n0 + i, k = k0 + x;
        if (nn < N && k < K) Wt[(size_t)nn * K + k] = __float2half_rn(t[x][i]);
    }
}

// ---------------- FP16 mma.sync GEMM (m16n8k16), cp.async pipelined -----------
// C = A(fp16) * W(fp16)^T, fp32 accumulate. BM=128, BN=128, BK=32.
#define S4 20
#define PLANE_WORDS (128 * S4)
#define STAGE_WORDS (2 * PLANE_WORDS)          // A, B
#define GEMM_SMEM_BYTES (2 * STAGE_WORDS * 4)  // 40960 B double buffered

__device__ __forceinline__ void mma16h(float* d, const uint32_t* a, const uint32_t* b) {
    asm volatile(
        "mma.sync.aligned.m16n8k16.row.col.f32.f16.f16.f32 "
        "{%0,%1,%2,%3}, {%4,%5,%6,%7}, {%8,%9}, {%0,%1,%2,%3};"
        : "+f"(d[0]), "+f"(d[1]), "+f"(d[2]), "+f"(d[3])
        : "r"(a[0]), "r"(a[1]), "r"(a[2]), "r"(a[3]), "r"(b[0]), "r"(b[1]));
}
__device__ __forceinline__ void cp_async16(uint32_t dst, const void* src, int sz) {
    asm volatile("cp.async.ca.shared.global [%0], [%1], 16, %2;"
                 :: "r"(dst), "l"(src), "r"(sz) : "memory");
}

// mode: 0 = fp32 out (C), 2 = fp16 out (Oh)
__global__ __launch_bounds__(256, 2) void gemm_h1_kernel(
    const uint32_t* __restrict__ Ah, const uint32_t* __restrict__ Bh,
    const float* __restrict__ bias, float* __restrict__ C,
    uint32_t* __restrict__ Oh,
    int M, int K, int Nfull, int act, int mode)
{
    extern __shared__ uint32_t smw[];
    uint32_t sb = smem_u32(smw);
    int tid = threadIdx.x;
    int wid = tid >> 5, lid = tid & 31;
    int wm = wid >> 2;
    int wn = wid & 3;
    int g  = lid >> 2;
    int tg = lid & 3;
    int m0 = blockIdx.y * 128;
    int n0 = blockIdx.x * 128;
    int Kw = K >> 1;

    float acc[4][4][4];
#pragma unroll
    for (int mi = 0; mi < 4; mi++)
#pragma unroll
        for (int ni = 0; ni < 4; ni++)
#pragma unroll
            for (int q = 0; q < 4; q++) acc[mi][ni][q] = 0.f;

    int KT = K >> 5;

    auto load_tile = [&](int kt, int b) {
        int kw = kt << 4;
        uint32_t base = sb + (uint32_t)(b * STAGE_WORDS) * 4u;
#pragma unroll
        for (int q = 0; q < 2; q++) {
            int i = tid + q * 256;
            int r = i >> 2, c = i & 3;
            uint32_t doff = (uint32_t)(r * S4 + c * 4) * 4u;
            bool okA = (m0 + r) < M;
            cp_async16(base + doff, Ah + (size_t)(m0 + r) * Kw + kw + c * 4, okA ? 16 : 0);
            bool okB = (n0 + r) < Nfull;
            cp_async16(base + PLANE_WORDS * 4u + doff,
                       Bh + (size_t)(n0 + r) * Kw + kw + c * 4, okB ? 16 : 0);
        }
    };

    load_tile(0, 0);
    asm volatile("cp.async.commit_group;" ::: "memory");
    if (KT > 1) load_tile(1, 1);
    asm volatile("cp.async.commit_group;" ::: "memory");

    for (int kt = 0; kt < KT; kt++) {
        asm volatile("cp.async.wait_group 1;" ::: "memory");
        __syncthreads();
        const uint32_t* AH = smw + (kt & 1) * STAGE_WORDS;
        const uint32_t* BH = AH + PLANE_WORDS;

#pragma unroll
        for (int kk = 0; kk < 2; kk++) {
            int kb = kk * 8;
            uint32_t ah[4][4], bh[4][2];
#pragma unroll
            for (int mi = 0; mi < 4; mi++) {
                int rb = wm * 64 + mi * 16;
                int o0 = (rb + g) * S4 + kb + tg;
                int o1 = (rb + g + 8) * S4 + kb + tg;
                ah[mi][0] = AH[o0]; ah[mi][1] = AH[o1];
                ah[mi][2] = AH[o0 + 4]; ah[mi][3] = AH[o1 + 4];
            }
#pragma unroll
            for (int ni = 0; ni < 4; ni++) {
                int nb = wn * 32 + ni * 8;
                int o = (nb + g) * S4 + kb + tg;
                bh[ni][0] = BH[o]; bh[ni][1] = BH[o + 4];
            }
#pragma unroll
            for (int mi = 0; mi < 4; mi++)
#pragma unroll
                for (int ni = 0; ni < 4; ni++)
                    mma16h(acc[mi][ni], ah[mi], bh[ni]);
        }
        __syncthreads();
        if (kt + 2 < KT) load_tile(kt + 2, kt & 1);
        asm volatile("cp.async.commit_group;" ::: "memory");
    }

    // epilogue
#pragma unroll
    for (int mi = 0; mi < 4; mi++) {
        int row0 = m0 + wm * 64 + mi * 16 + g;
        int row1 = row0 + 8;
#pragma unroll
        for (int ni = 0; ni < 4; ni++) {
            int col = n0 + wn * 32 + ni * 8 + 2 * tg;
            if (col >= Nfull) continue;
            float bx = 0.f, by = 0.f;
            if (bias) { bx = bias[col]; by = bias[col + 1]; }
#pragma unroll
            for (int h = 0; h < 2; h++) {
                int row = h ? row1 : row0;
                if (row >= M) continue;
                float vx = acc[mi][ni][h * 2 + 0] + bx;
                float vy = acc[mi][ni][h * 2 + 1] + by;
                if (act == 1) { vx = fmaxf(vx, 0.f); vy = fmaxf(vy, 0.f); }
                else if (act == 2) {
                    vx = vx > 0.f ? vx : 0.01f * vx;
                    vy = vy > 0.f ? vy : 0.01f * vy;
                }
                if (mode == 2) {
                    half2 hv = __float22half2_rn(make_float2(vx, vy));
                    Oh[(size_t)row * (Nfull >> 1) + (col >> 1)] = *(uint32_t*)&hv;
                } else {
                    *(float2*)(C + (size_t)row * Nfull + col) = make_float2(vx, vy);
                }
            }
        }
    }
}

// ---------------- pool tail ----------------------------------------------------
__global__ void pool_fin_kernel(float* out) {
    int i = blockIdx.x * blockDim.x + threadIdx.x;
    if (i < N_GRAPHS * 32) {
        int b = i >> 5;
        out[i] = g_pool[i] / fmaxf((float)g_pcnt[b], 1.0f);
    }
}

// ---------------- host driver --------------------------------------------------
static inline int cdiv(int a, int b) { return (a + b - 1) / b; }

static void spmm_h_launch(const uint4* in, uint4* out,
                          const float* bias, int act, int W, int n) {
    int W8 = W / 8;
    int ypb = 128 / W8; if (ypb < 1) ypb = 1;
    dim3 blk(W8, ypb);
    spmm_h_kernel<<<cdiv(n, ypb), blk>>>(in, out, bias, act, W8, n);
}

extern "C" void kernel_launch(void* const* d_in, const int* in_sizes, int n_in,
                              void* d_out, int out_size) {
    const float* x     = (const float*)d_in[0];
    const void*  edge  = d_in[1];
    const void*  batch = d_in[2];
    TParams tp;
    const float* bl[9];
    for (int i = 0; i < 9; i++) {
        tp.W[i] = (const float*)d_in[3 + 2 * i];
        bl[i]   = (const float*)d_in[4 + 2 * i];
    }
    int n = in_sizes[2];
    int E = in_sizes[1] / 2;

    float *F;
    uint4 *H0, *H1, *Ht, *whh;
    cudaGetSymbolAddress((void**)&F,   g_F);
    cudaGetSymbolAddress((void**)&H0,  g_H0);
    cudaGetSymbolAddress((void**)&H1,  g_H1);
    cudaGetSymbolAddress((void**)&Ht,  g_Ht);
    cudaGetSymbolAddress((void**)&whh, g_whh);

    cudaFuncSetAttribute(gemm_h1_kernel, cudaFuncAttributeMaxDynamicSharedMemorySize,
                         GEMM_SMEM_BYTES);

    // --- setup: CSR build + fp16 weight transpose + x->fp16 ---
    setup_kernel<<<cdiv(n, 256), 256>>>(edge, batch, n);
    transpose_all_kernel<<<dim3(16, 16, 9), dim3(32, 8)>>>(tp, (__half*)whh);
    f2h_kernel<<<cdiv(n * 64, 256), 256>>>((const float2*)x, (uint32_t*)H0, (long)n * 64);
    count_kernel<<<cdiv(E, 256), 256>>>(edge, E);
    scan_kernel<<<1, 1024>>>(n);
    fill_kernel<<<cdiv(E + n, 256), 256>>>(edge, E, n);

    // --- layers ---
    static const int widths[10]  = {128, 128, 256, 384, 512, 512, 384, 256, 128, 32};
    static const int acts[9]     = {1, 1, 2, 1, 2, 2, 1, 1, 0};
    static const int aggfirst[9] = {1, 1, 1, 1, 1, 0, 0, 0, 0};

    const uint4* Hin = H0;
    uint4* pong[2] = {H1, H0};
    int pp = 0;
    for (int l = 0; l < 9; l++) {
        int K = widths[l], N = widths[l + 1];
        const uint32_t* wl = (const uint32_t*)whh + (size_t)l * WMAX * WMAX / 2;
        dim3 grid(cdiv(N, 128), cdiv(n, 128));
        uint4* Hout = pong[pp];
        if (aggfirst[l]) {
            spmm_h_launch(Hin, Ht, nullptr, 0, K, n);
            gemm_h1_kernel<<<grid, 256, GEMM_SMEM_BYTES>>>(
                (const uint32_t*)Ht, wl, bl[l], nullptr, (uint32_t*)Hout,
                n, K, N, acts[l], 2);
            Hin = Hout; pp ^= 1;
        } else if (l < 8) {
            gemm_h1_kernel<<<grid, 256, GEMM_SMEM_BYTES>>>(
                (const uint32_t*)Hin, wl, nullptr, nullptr, (uint32_t*)Ht,
                n, K, N, 0, 2);
            spmm_h_launch(Ht, Hout, bl[l], acts[l], N, n);
            Hin = Hout; pp ^= 1;
        } else {
            gemm_h1_kernel<<<grid, 256, GEMM_SMEM_BYTES>>>(
                (const uint32_t*)Hin, wl, nullptr, F, nullptr,
                n, K, N, 0, 0);
            spmm_pool_kernel<<<cdiv(n, 4), dim3(32, 4)>>>(F, batch, bl[8], n);
        }
    }

    // --- pool finalize ---
    pool_fin_kernel<<<cdiv(N_GRAPHS * 32, 256), 256>>>((float*)d_out);
}